// round 14
// baseline (speedup 1.0000x reference)
#include <cuda_runtime.h>
#include <cstdint>

// YOLO loss: persistent cp.async 3-stage pipelined reduction.
// R2 structure (proven: 29.1us kernel @ 6.2TB/s) with TILE 64->56 to raise
// residency from 5 to 6 blocks/SM (smem 42.2KB -> 36.96KB per block).
// preds:   [802816 cells x 30 ch] float32 (96.3 MB)
// targets: [802816 cells x 25 ch] float32 (80.3 MB)

#define THREADS 64
#define TILE 56                       // cells per tile; 802816/56 = 14336 exact
#define STAGES 3
#define PRED_F4 (TILE * 30 / 4)       // 420 float4 per tile
#define TGT_F4  (TILE * 25 / 4)       // 350 float4 per tile
#define STAGE_FLOATS (TILE * 55)      // 3080 floats = 12320 B per stage
#define GRID 888                      // 148 SMs x 6 blocks persistent

#define LAMBDA_COORD 5.0f
#define LAMBDA_NOOBJ 0.5f

__global__ void yolo_zero_kernel(float* out) {
    if (threadIdx.x == 0) out[0] = 0.0f;
}

__device__ __forceinline__ void cp16(uint32_t smem_addr, const float4* gptr) {
    asm volatile("cp.async.cg.shared.global [%0], [%1], 16;"
                 :: "r"(smem_addr), "l"(gptr));
}

__global__ __launch_bounds__(THREADS)
void yolo_loss_kernel(const float* __restrict__ preds,
                      const float* __restrict__ targets,
                      float* __restrict__ out,
                      int ntiles) {
    __shared__ float buf[STAGES * STAGE_FLOATS];   // 36960 B -> 6 blocks/SM
    __shared__ float wsum[THREADS / 32];

    const int tid = threadIdx.x;
    const int grid = gridDim.x;
    const uint32_t sbase = (uint32_t)__cvta_generic_to_shared(buf);

    // Issue async loads for one tile into one stage; always commit a group
    // (possibly empty) so group counting stays uniform across iterations.
    auto issue = [&](int tile, int stage) {
        if (tile < ntiles) {
            const float4* pg = reinterpret_cast<const float4*>(preds)
                               + (size_t)tile * PRED_F4;
            const uint32_t sp = sbase + (uint32_t)stage * (STAGE_FLOATS * 4);
            for (int idx = tid; idx < PRED_F4; idx += THREADS)
                cp16(sp + idx * 16, pg + idx);
            const float4* tg = reinterpret_cast<const float4*>(targets)
                               + (size_t)tile * TGT_F4;
            const uint32_t st = sp + TILE * 30 * 4;
            for (int idx = tid; idx < TGT_F4; idx += THREADS)
                cp16(st + idx * 16, tg + idx);
        }
        asm volatile("cp.async.commit_group;");
    };

    // Prologue: prefetch 2 tiles deep.
    issue((int)blockIdx.x, 0);
    issue((int)blockIdx.x + grid, 1);

    float acc = 0.0f;
    int i = 0;
    for (int t = (int)blockIdx.x; t < ntiles; t += grid, i++) {
        const int stage = i % STAGES;

        asm volatile("cp.async.wait_group 1;");   // tile t's group complete
        __syncthreads();

        if (tid < TILE) {
            const float* p  = buf + stage * STAGE_FLOATS + tid * 30;
            const float* tg = buf + stage * STAGE_FLOATS + TILE * 30 + tid * 25;

            const float s0 = p[0];
            const float s1 = p[5];
            const int off = (s1 > s0) ? 5 : 0;   // argmax, first-max tiebreak

            float loss;
            if (tg[0] == 1.0f) {
                float box_loss = 0.0f;
                #pragma unroll
                for (int k = 1; k < 5; k++) {
                    const float d = p[off + k] - tg[k];
                    box_loss = fmaf(d, d, box_loss);
                }
                const float dpc = p[off] - 1.0f;   // tg[0] == 1 exactly
                float class_loss = 0.0f;
                #pragma unroll
                for (int j = 0; j < 20; j++) {
                    const float d = p[10 + j] - tg[5 + j];
                    class_loss = fmaf(d, d, class_loss);
                }
                loss = fmaf(LAMBDA_COORD, box_loss, fmaf(dpc, dpc, class_loss));
            } else {
                loss = LAMBDA_NOOBJ * (s0 * s0 + s1 * s1);
            }
            acc += loss;
        }

        __syncthreads();                       // stage buffer free for reuse
        issue(t + 2 * grid, (i + 2) % STAGES); // prefetch 2 ahead
    }

    asm volatile("cp.async.wait_group 0;");    // drain (empty tails)

    // Block reduce once, single atomic per block (888 total).
    #pragma unroll
    for (int o = 16; o > 0; o >>= 1)
        acc += __shfl_xor_sync(0xffffffffu, acc, o);
    if ((tid & 31) == 0) wsum[tid >> 5] = acc;
    __syncthreads();
    if (tid == 0) atomicAdd(out, wsum[0] + wsum[1]);
}

extern "C" void kernel_launch(void* const* d_in, const int* in_sizes, int n_in,
                              void* d_out, int out_size) {
    const float* preds   = (const float*)d_in[0];
    const float* targets = (const float*)d_in[1];
    float* out = (float*)d_out;

    const int ncells = in_sizes[0] / 30;       // 802816
    const int ntiles = ncells / TILE;          // 14336

    yolo_zero_kernel<<<1, 32>>>(out);
    yolo_loss_kernel<<<GRID, THREADS>>>(preds, targets, out, ntiles);
}

// round 15
// speedup vs baseline: 1.0457x; 1.0457x over previous
#include <cuda_runtime.h>
#include <cstdint>

// YOLO loss: persistent cp.async 3-stage pipelined reduction.
// FINAL — best measured configuration, verified twice (31.23us / 31.49us
// total; kernel 29.1us @ 6.21TB/s ≈ 98% of the achieved dual-stream
// streaming ceiling on this part). Probed and rejected: 4-stage, 2-stage/128t,
// TILE=56 6blk/SM, TMA-bulk, issue-before-compute, fused last-block finalize,
// memset graph node, sector-skipping direct-LDG gather — all equal or worse.
// preds:   [802816 cells x 30 ch] float32 (96.3 MB)
// targets: [802816 cells x 25 ch] float32 (80.3 MB)

#define THREADS 64
#define TILE 64                       // cells per tile
#define STAGES 3
#define PRED_F4 (TILE * 30 / 4)       // 480 float4 per tile
#define TGT_F4  (TILE * 25 / 4)       // 400 float4 per tile
#define STAGE_FLOATS (TILE * 55)      // 3520 floats = 14080 B per stage
#define GRID 760                      // ~5 blocks/SM persistent

#define LAMBDA_COORD 5.0f
#define LAMBDA_NOOBJ 0.5f

__global__ void yolo_zero_kernel(float* out) {
    if (threadIdx.x == 0) out[0] = 0.0f;
}

__device__ __forceinline__ void cp16(uint32_t smem_addr, const float4* gptr) {
    asm volatile("cp.async.cg.shared.global [%0], [%1], 16;"
                 :: "r"(smem_addr), "l"(gptr));
}

__global__ __launch_bounds__(THREADS)
void yolo_loss_kernel(const float* __restrict__ preds,
                      const float* __restrict__ targets,
                      float* __restrict__ out,
                      int ntiles) {
    __shared__ float buf[STAGES * STAGE_FLOATS];   // 42240 B
    __shared__ float wsum[THREADS / 32];

    const int tid = threadIdx.x;
    const int grid = gridDim.x;
    const uint32_t sbase = (uint32_t)__cvta_generic_to_shared(buf);

    // Issue async loads for one tile into one stage; always commit a group
    // (possibly empty) so group counting stays uniform across iterations.
    auto issue = [&](int tile, int stage) {
        if (tile < ntiles) {
            const float4* pg = reinterpret_cast<const float4*>(preds)
                               + (size_t)tile * PRED_F4;
            const uint32_t sp = sbase + (uint32_t)stage * (STAGE_FLOATS * 4);
            for (int idx = tid; idx < PRED_F4; idx += THREADS)
                cp16(sp + idx * 16, pg + idx);
            const float4* tg = reinterpret_cast<const float4*>(targets)
                               + (size_t)tile * TGT_F4;
            const uint32_t st = sp + TILE * 30 * 4;
            for (int idx = tid; idx < TGT_F4; idx += THREADS)
                cp16(st + idx * 16, tg + idx);
        }
        asm volatile("cp.async.commit_group;");
    };

    // Prologue: prefetch 2 tiles deep.
    issue((int)blockIdx.x, 0);
    issue((int)blockIdx.x + grid, 1);

    float acc = 0.0f;
    int i = 0;
    for (int t = (int)blockIdx.x; t < ntiles; t += grid, i++) {
        const int stage = i % STAGES;

        asm volatile("cp.async.wait_group 1;");   // tile t's group complete
        __syncthreads();

        const float* p  = buf + stage * STAGE_FLOATS + tid * 30;
        const float* tg = buf + stage * STAGE_FLOATS + TILE * 30 + tid * 25;

        const float s0 = p[0];
        const float s1 = p[5];
        const int off = (s1 > s0) ? 5 : 0;   // argmax, first-max tiebreak

        float loss;
        if (tg[0] == 1.0f) {
            float box_loss = 0.0f;
            #pragma unroll
            for (int k = 1; k < 5; k++) {
                const float d = p[off + k] - tg[k];
                box_loss = fmaf(d, d, box_loss);
            }
            const float dpc = p[off] - 1.0f;   // tg[0] == 1 exactly
            float class_loss = 0.0f;
            #pragma unroll
            for (int j = 0; j < 20; j++) {
                const float d = p[10 + j] - tg[5 + j];
                class_loss = fmaf(d, d, class_loss);
            }
            loss = fmaf(LAMBDA_COORD, box_loss, fmaf(dpc, dpc, class_loss));
        } else {
            loss = LAMBDA_NOOBJ * (s0 * s0 + s1 * s1);
        }
        acc += loss;

        __syncthreads();                       // stage buffer free for reuse
        issue(t + 2 * grid, (i + 2) % STAGES); // prefetch 2 ahead
    }

    asm volatile("cp.async.wait_group 0;");    // drain (empty tails)

    // Block reduce once, single atomic per block (760 total).
    #pragma unroll
    for (int o = 16; o > 0; o >>= 1)
        acc += __shfl_xor_sync(0xffffffffu, acc, o);
    if ((tid & 31) == 0) wsum[tid >> 5] = acc;
    __syncthreads();
    if (tid == 0) atomicAdd(out, wsum[0] + wsum[1]);
}

extern "C" void kernel_launch(void* const* d_in, const int* in_sizes, int n_in,
                              void* d_out, int out_size) {
    const float* preds   = (const float*)d_in[0];
    const float* targets = (const float*)d_in[1];
    float* out = (float*)d_out;

    const int ncells = in_sizes[0] / 30;       // 802816
    const int ntiles = ncells / TILE;          // 12544

    yolo_zero_kernel<<<1, 32>>>(out);
    yolo_loss_kernel<<<GRID, THREADS>>>(preds, targets, out, ntiles);
}

// round 16
// speedup vs baseline: 1.0543x; 1.0082x over previous
#include <cuda_runtime.h>
#include <cstdint>

// YOLO loss: persistent cp.async 3-stage pipelined reduction.
// Verified-best structure (R2/R12/R14: kernel 29.1-29.5us @ 6.2TB/s).
// Single change: GRID 760 -> 740 = exactly 5 resident blocks x 148 SMs,
// eliminating the 20-block second wave (a ~9MB low-parallelism tail).
// preds:   [802816 cells x 30 ch] float32 (96.3 MB)
// targets: [802816 cells x 25 ch] float32 (80.3 MB)

#define THREADS 64
#define TILE 64                       // cells per tile
#define STAGES 3
#define PRED_F4 (TILE * 30 / 4)       // 480 float4 per tile
#define TGT_F4  (TILE * 25 / 4)       // 400 float4 per tile
#define STAGE_FLOATS (TILE * 55)      // 3520 floats = 14080 B per stage
#define GRID 740                      // 148 SMs x 5 blocks, single wave

#define LAMBDA_COORD 5.0f
#define LAMBDA_NOOBJ 0.5f

__global__ void yolo_zero_kernel(float* out) {
    if (threadIdx.x == 0) out[0] = 0.0f;
}

__device__ __forceinline__ void cp16(uint32_t smem_addr, const float4* gptr) {
    asm volatile("cp.async.cg.shared.global [%0], [%1], 16;"
                 :: "r"(smem_addr), "l"(gptr));
}

__global__ __launch_bounds__(THREADS)
void yolo_loss_kernel(const float* __restrict__ preds,
                      const float* __restrict__ targets,
                      float* __restrict__ out,
                      int ntiles) {
    __shared__ float buf[STAGES * STAGE_FLOATS];   // 42240 B
    __shared__ float wsum[THREADS / 32];

    const int tid = threadIdx.x;
    const int grid = gridDim.x;
    const uint32_t sbase = (uint32_t)__cvta_generic_to_shared(buf);

    // Issue async loads for one tile into one stage; always commit a group
    // (possibly empty) so group counting stays uniform across iterations.
    auto issue = [&](int tile, int stage) {
        if (tile < ntiles) {
            const float4* pg = reinterpret_cast<const float4*>(preds)
                               + (size_t)tile * PRED_F4;
            const uint32_t sp = sbase + (uint32_t)stage * (STAGE_FLOATS * 4);
            for (int idx = tid; idx < PRED_F4; idx += THREADS)
                cp16(sp + idx * 16, pg + idx);
            const float4* tg = reinterpret_cast<const float4*>(targets)
                               + (size_t)tile * TGT_F4;
            const uint32_t st = sp + TILE * 30 * 4;
            for (int idx = tid; idx < TGT_F4; idx += THREADS)
                cp16(st + idx * 16, tg + idx);
        }
        asm volatile("cp.async.commit_group;");
    };

    // Prologue: prefetch 2 tiles deep.
    issue((int)blockIdx.x, 0);
    issue((int)blockIdx.x + grid, 1);

    float acc = 0.0f;
    int i = 0;
    for (int t = (int)blockIdx.x; t < ntiles; t += grid, i++) {
        const int stage = i % STAGES;

        asm volatile("cp.async.wait_group 1;");   // tile t's group complete
        __syncthreads();

        const float* p  = buf + stage * STAGE_FLOATS + tid * 30;
        const float* tg = buf + stage * STAGE_FLOATS + TILE * 30 + tid * 25;

        const float s0 = p[0];
        const float s1 = p[5];
        const int off = (s1 > s0) ? 5 : 0;   // argmax, first-max tiebreak

        float loss;
        if (tg[0] == 1.0f) {
            float box_loss = 0.0f;
            #pragma unroll
            for (int k = 1; k < 5; k++) {
                const float d = p[off + k] - tg[k];
                box_loss = fmaf(d, d, box_loss);
            }
            const float dpc = p[off] - 1.0f;   // tg[0] == 1 exactly
            float class_loss = 0.0f;
            #pragma unroll
            for (int j = 0; j < 20; j++) {
                const float d = p[10 + j] - tg[5 + j];
                class_loss = fmaf(d, d, class_loss);
            }
            loss = fmaf(LAMBDA_COORD, box_loss, fmaf(dpc, dpc, class_loss));
        } else {
            loss = LAMBDA_NOOBJ * (s0 * s0 + s1 * s1);
        }
        acc += loss;

        __syncthreads();                       // stage buffer free for reuse
        issue(t + 2 * grid, (i + 2) % STAGES); // prefetch 2 ahead
    }

    asm volatile("cp.async.wait_group 0;");    // drain (empty tails)

    // Block reduce once, single atomic per block (740 total).
    #pragma unroll
    for (int o = 16; o > 0; o >>= 1)
        acc += __shfl_xor_sync(0xffffffffu, acc, o);
    if ((tid & 31) == 0) wsum[tid >> 5] = acc;
    __syncthreads();
    if (tid == 0) atomicAdd(out, wsum[0] + wsum[1]);
}

extern "C" void kernel_launch(void* const* d_in, const int* in_sizes, int n_in,
                              void* d_out, int out_size) {
    const float* preds   = (const float*)d_in[0];
    const float* targets = (const float*)d_in[1];
    float* out = (float*)d_out;

    const int ncells = in_sizes[0] / 30;       // 802816
    const int ntiles = ncells / TILE;          // 12544

    yolo_zero_kernel<<<1, 32>>>(out);
    yolo_loss_kernel<<<GRID, THREADS>>>(preds, targets, out, ntiles);
}